// round 12
// baseline (speedup 1.0000x reference)
#include <cuda_runtime.h>
#include <math.h>

// Problem constants
#define BATCH 2048
#define HID   1024
#define NDIM  4096          // 4*HID
#define KHALF 1024          // INPUT_SIZE == HIDDEN_SIZE
#define KTOT  2048

// GEMM tiling
#define BM 128
#define BN 128
#define BK 16
#define SPAD 20             // smem row stride in 4B words (conflict-free staging)
#define NIT (KTOT / BK)     // 128 k-iterations total (64 per half)

// 32 MB scratch for preact (static device array: no runtime alloc)
__device__ float g_preact[(size_t)BATCH * NDIM];

__device__ __forceinline__ unsigned f2tf32(float f) {
    unsigned u;
    asm("cvt.rna.tf32.f32 %0, %1;" : "=r"(u) : "f"(f));
    return u;
}

__device__ __forceinline__ void mma_tf32(float& d0, float& d1, float& d2, float& d3,
                                         unsigned a0, unsigned a1, unsigned a2, unsigned a3,
                                         unsigned b0, unsigned b1) {
    asm volatile("mma.sync.aligned.m16n8k8.row.col.f32.tf32.tf32.f32 "
                 "{%0,%1,%2,%3}, {%4,%5,%6,%7}, {%8,%9}, {%0,%1,%2,%3};\n"
                 : "+f"(d0), "+f"(d1), "+f"(d2), "+f"(d3)
                 : "r"(a0), "r"(a1), "r"(a2), "r"(a3), "r"(b0), "r"(b1));
}

// ---------------------------------------------------------------------------
// preact = [x|h] @ [W_ih|W_hh]^T  via tf32 tensor-core mma (TN GEMM).
//
// smem k-permutation: logical k (0..15) stored at slot k' = (k%4)*4 + k/4,
// i.e. slot 4*tg+q holds logical k = tg + 4q. One LDS.128 at [row][4*tg]
// yields k = {tg, tg+4, tg+8, tg+12}: (.x,.y) feed mma k-step 0, (.z,.w)
// feed k-step 1. STS staging addr = 20*r + c0 covers all 32 banks per warp.
// ---------------------------------------------------------------------------
struct GemmState {
    float4 a_ld[2], b_ld[2];
};

__device__ __forceinline__ void gemm_gload(GemmState& st,
                                           const float* __restrict__ Ap,
                                           const float* __restrict__ Bp,
                                           int bm, int bn, int kk,
                                           int r0, int c0) {
#pragma unroll
    for (int i = 0; i < 2; i++) {
        const int r = r0 + i * 64;
        st.a_ld[i] = *reinterpret_cast<const float4*>(&Ap[(size_t)(bm + r) * KHALF + kk + 4 * c0]);
        st.b_ld[i] = *reinterpret_cast<const float4*>(&Bp[(size_t)(bn + r) * KHALF + kk + 4 * c0]);
    }
}

__device__ __forceinline__ void gemm_stage(const GemmState& st,
                                           unsigned* __restrict__ As,
                                           unsigned* __restrict__ Bs,
                                           int r0, int c0) {
#pragma unroll
    for (int i = 0; i < 2; i++) {
        const int r = r0 + i * 64;
        unsigned* da = &As[r * SPAD + c0];
        da[0]  = f2tf32(st.a_ld[i].x);
        da[4]  = f2tf32(st.a_ld[i].y);
        da[8]  = f2tf32(st.a_ld[i].z);
        da[12] = f2tf32(st.a_ld[i].w);
        unsigned* db = &Bs[r * SPAD + c0];
        db[0]  = f2tf32(st.b_ld[i].x);
        db[4]  = f2tf32(st.b_ld[i].y);
        db[8]  = f2tf32(st.b_ld[i].z);
        db[12] = f2tf32(st.b_ld[i].w);
    }
}

__global__ __launch_bounds__(256, 1)
void lstm_gemm_tf32_kernel(const float* __restrict__ x,
                           const float* __restrict__ h,
                           const float* __restrict__ Wih,
                           const float* __restrict__ Whh)
{
    __shared__ unsigned As[2][BM * SPAD];   // 2 x 10240 B
    __shared__ unsigned Bs[2][BN * SPAD];   // 2 x 10240 B  -> 40 KB total

    const int tid = threadIdx.x;
    const int bm  = blockIdx.y * BM;
    const int bn  = blockIdx.x * BN;

    const int wid    = tid >> 5;
    const int warp_m = wid >> 2;        // 0..1  (64 rows each)
    const int warp_n = wid & 3;         // 0..3  (32 cols each)
    const int lane   = tid & 31;
    const int g      = lane >> 2;       // 0..7
    const int tg     = lane & 3;        // 0..3

    // staging coords: 2 float4 of A and 2 of B per thread per iter
    const int r0 = tid >> 2;            // rows 0..63
    const int c0 = tid & 3;             // float4 col 0..3

    float acc[4][4][4];
#pragma unroll
    for (int mt = 0; mt < 4; mt++)
#pragma unroll
        for (int nt = 0; nt < 4; nt++)
#pragma unroll
            for (int i = 0; i < 4; i++) acc[mt][nt][i] = 0.f;

    GemmState st;

    // ---- prologue: load + stage k-tile 0 ----
    gemm_gload(st, x, Wih, bm, bn, 0, r0, c0);
    gemm_stage(st, As[0], Bs[0], r0, c0);
    __syncthreads();

    int buf = 0;
    // Two halves with hoisted source pointers: [x,Wih] then [h,Whh].
#pragma unroll 1
    for (int half = 0; half < 2; ++half) {
        const float* Ap = half ? h   : x;
        const float* Bp = half ? Whh : Wih;

#pragma unroll 1
        for (int it = 0; it < NIT / 2; ++it) {
            const bool last_in_half = (it == NIT / 2 - 1);
            const bool has_next     = (!last_in_half) | (half == 0);

            // prefetch next k-tile into registers
            if (!last_in_half) {
                gemm_gload(st, Ap, Bp, bm, bn, (it + 1) * BK, r0, c0);
            } else if (!half) {
                gemm_gload(st, h, Whh, bm, bn, 0, r0, c0);
            }

            // ---- compute on current buffer: BK=16 -> 2 k-steps ----
            uint4 afr[4][2];
            uint4 bfr[4];
#pragma unroll
            for (int mt = 0; mt < 4; mt++) {
                const int rr = warp_m * 64 + mt * 16 + g;
                afr[mt][0] = *reinterpret_cast<const uint4*>(&As[buf][rr * SPAD + tg * 4]);
                afr[mt][1] = *reinterpret_cast<const uint4*>(&As[buf][(rr + 8) * SPAD + tg * 4]);
            }
#pragma unroll
            for (int nt = 0; nt < 4; nt++) {
                const int cc = warp_n * 32 + nt * 8 + g;
                bfr[nt] = *reinterpret_cast<const uint4*>(&Bs[buf][cc * SPAD + tg * 4]);
            }
#pragma unroll
            for (int mt = 0; mt < 4; mt++) {
#pragma unroll
                for (int nt = 0; nt < 4; nt++) {
                    mma_tf32(acc[mt][nt][0], acc[mt][nt][1], acc[mt][nt][2], acc[mt][nt][3],
                             afr[mt][0].x, afr[mt][1].x, afr[mt][0].y, afr[mt][1].y,
                             bfr[nt].x, bfr[nt].y);
                    mma_tf32(acc[mt][nt][0], acc[mt][nt][1], acc[mt][nt][2], acc[mt][nt][3],
                             afr[mt][0].z, afr[mt][1].z, afr[mt][0].w, afr[mt][1].w,
                             bfr[nt].z, bfr[nt].w);
                }
            }

            // ---- stage next tile into the other buffer ----
            if (has_next) {
                const int nb = buf ^ 1;
                gemm_stage(st, As[nb], Bs[nb], r0, c0);
                __syncthreads();
                buf = nb;
            }
        }
    }

    // ---- epilogue: write accumulators (c0,c1 at row g; c2,c3 at row g+8) ----
#pragma unroll
    for (int mt = 0; mt < 4; mt++) {
#pragma unroll
        for (int nt = 0; nt < 4; nt++) {
            const int gr = bm + warp_m * 64 + mt * 16 + g;
            const int gc = bn + warp_n * 32 + nt * 8 + 2 * tg;
            float2 v0 = make_float2(acc[mt][nt][0], acc[mt][nt][1]);
            float2 v1 = make_float2(acc[mt][nt][2], acc[mt][nt][3]);
            *reinterpret_cast<float2*>(&g_preact[(size_t)gr * NDIM + gc]) = v0;
            *reinterpret_cast<float2*>(&g_preact[(size_t)(gr + 8) * NDIM + gc]) = v1;
        }
    }
}

// ---------------------------------------------------------------------------
// Kernel 2: gates + cell update + LayerNorm + outputs. One block per row.
// ---------------------------------------------------------------------------
__device__ __forceinline__ float sigmoidf_(float v) {
    return 1.f / (1.f + __expf(-v));
}

__global__ __launch_bounds__(256)
void lstm_cell_ln_kernel(const float* __restrict__ c_in,
                         const float* __restrict__ b_ih,
                         const float* __restrict__ b_hh,
                         const float* __restrict__ ln_w,
                         const float* __restrict__ ln_b,
                         float* __restrict__ h_out,
                         float* __restrict__ c_out)
{
    const int row = blockIdx.x;
    const int tid = threadIdx.x;
    const float* P = g_preact + (size_t)row * NDIM;

    float ct[4], og[4];
    float s = 0.f, s2 = 0.f;

#pragma unroll
    for (int t = 0; t < 4; t++) {
        const int col = tid + t * 256;
        const float pi = P[col]           + __ldg(&b_ih[col])           + __ldg(&b_hh[col]);
        const float pf = P[col + HID]     + __ldg(&b_ih[col + HID])     + __ldg(&b_hh[col + HID]);
        const float po = P[col + 2 * HID] + __ldg(&b_ih[col + 2 * HID]) + __ldg(&b_hh[col + 2 * HID]);
        const float pg = P[col + 3 * HID] + __ldg(&b_ih[col + 3 * HID]) + __ldg(&b_hh[col + 3 * HID]);

        const float ig = sigmoidf_(pi);
        const float fg = sigmoidf_(pf);
        og[t]          = sigmoidf_(po);
        const float gg = tanhf(pg);

        const float cv = c_in[(size_t)row * HID + col] * fg + ig * gg;
        ct[t] = cv;
        s  += cv;
        s2 += cv * cv;
    }

#pragma unroll
    for (int o = 16; o > 0; o >>= 1) {
        s  += __shfl_xor_sync(0xffffffffu, s,  o);
        s2 += __shfl_xor_sync(0xffffffffu, s2, o);
    }
    __shared__ float ws[8], ws2[8];
    const int lane = tid & 31, wid = tid >> 5;
    if (lane == 0) { ws[wid] = s; ws2[wid] = s2; }
    __syncthreads();
    s = 0.f; s2 = 0.f;
#pragma unroll
    for (int w = 0; w < 8; w++) { s += ws[w]; s2 += ws2[w]; }

    const float mu   = s * (1.f / HID);
    const float var  = fmaxf(s2 * (1.f / HID) - mu * mu, 0.f);
    const float rstd = rsqrtf(var + 1e-5f);

#pragma unroll
    for (int t = 0; t < 4; t++) {
        const int col = tid + t * 256;
        const float cn = (ct[t] - mu) * rstd * __ldg(&ln_w[col]) + __ldg(&ln_b[col]);
        c_out[(size_t)row * HID + col] = cn;
        h_out[(size_t)row * HID + col] = og[t] * tanhf(cn);
    }
}

// ---------------------------------------------------------------------------
extern "C" void kernel_launch(void* const* d_in, const int* in_sizes, int n_in,
                              void* d_out, int out_size)
{
    const float* x   = (const float*)d_in[0];
    const float* h   = (const float*)d_in[1];
    const float* c   = (const float*)d_in[2];
    const float* Wih = (const float*)d_in[3];
    const float* bih = (const float*)d_in[4];
    const float* Whh = (const float*)d_in[5];
    const float* bhh = (const float*)d_in[6];
    const float* lnw = (const float*)d_in[7];
    const float* lnb = (const float*)d_in[8];

    float* out   = (float*)d_out;
    float* h_out = out;                          // h_t first
    float* c_out = out + (size_t)BATCH * HID;    // then c_t

    dim3 ggrid(NDIM / BN, BATCH / BM);           // 32 x 16 = 512 blocks
    lstm_gemm_tf32_kernel<<<ggrid, 256>>>(x, h, Wih, Whh);
    lstm_cell_ln_kernel<<<BATCH, 256>>>(c, bih, bhh, lnw, lnb, h_out, c_out);
}

// round 15
// speedup vs baseline: 1.7037x; 1.7037x over previous
#include <cuda_runtime.h>
#include <cstdint>
#include <math.h>

// Problem constants
#define BATCH 2048
#define HID   1024
#define NDIM  4096          // 4*HID
#define KHALF 1024
#define KTOT  2048

// GEMM tiling
#define BM 128
#define BN 128
#define BK 16
#define NIT (KTOT / BK)     // 128 k-tiles
#define STAGES 3            // cp.async pipeline depth (3*16KB = 48KB smem exactly)

// Static device scratch (no runtime alloc): preact 32MB + packed tf32 inputs 48MB
__device__ float g_preact[(size_t)BATCH * NDIM];
__device__ float g_Acvt[(size_t)BATCH * KTOT];   // [x|h], tf32-rna, row-major 2048 wide
__device__ float g_Bcvt[(size_t)NDIM * KTOT];    // [Wih|Whh], tf32-rna, row-major 2048 wide

__device__ __forceinline__ unsigned f2tf32(float f) {
    unsigned u;
    asm("cvt.rna.tf32.f32 %0, %1;" : "=r"(u) : "f"(f));
    return u;
}

__device__ __forceinline__ void mma_tf32(float& d0, float& d1, float& d2, float& d3,
                                         unsigned a0, unsigned a1, unsigned a2, unsigned a3,
                                         unsigned b0, unsigned b1) {
    asm volatile("mma.sync.aligned.m16n8k8.row.col.f32.tf32.tf32.f32 "
                 "{%0,%1,%2,%3}, {%4,%5,%6,%7}, {%8,%9}, {%0,%1,%2,%3};\n"
                 : "+f"(d0), "+f"(d1), "+f"(d2), "+f"(d3)
                 : "r"(a0), "r"(a1), "r"(a2), "r"(a3), "r"(b0), "r"(b1));
}

// ---------------------------------------------------------------------------
// Kernel 0: convert inputs to tf32-rna and pack [x|h] / [Wih|Whh] contiguous.
// 3M float4 elements total (A': 1M, B': 2M).
// ---------------------------------------------------------------------------
__global__ __launch_bounds__(256)
void cvt_pack_kernel(const float* __restrict__ x,  const float* __restrict__ h,
                     const float* __restrict__ Wih, const float* __restrict__ Whh)
{
    const size_t nA = (size_t)BATCH * KTOT / 4;   // 1M float4
    const size_t nB = (size_t)NDIM  * KTOT / 4;   // 2M float4
    const size_t i  = (size_t)blockIdx.x * blockDim.x + threadIdx.x;
    if (i < nA) {
        const size_t r = i >> 9;            // 512 float4 per 2048-wide row
        const size_t q = i & 511;
        const float4 v = (q < 256) ? reinterpret_cast<const float4*>(x)[r * 256 + q]
                                   : reinterpret_cast<const float4*>(h)[r * 256 + (q - 256)];
        uint4 o;
        o.x = f2tf32(v.x); o.y = f2tf32(v.y); o.z = f2tf32(v.z); o.w = f2tf32(v.w);
        reinterpret_cast<uint4*>(g_Acvt)[i] = o;
    } else if (i < nA + nB) {
        const size_t j = i - nA;
        const size_t r = j >> 9;
        const size_t q = j & 511;
        const float4 v = (q < 256) ? reinterpret_cast<const float4*>(Wih)[r * 256 + q]
                                   : reinterpret_cast<const float4*>(Whh)[r * 256 + (q - 256)];
        uint4 o;
        o.x = f2tf32(v.x); o.y = f2tf32(v.y); o.z = f2tf32(v.z); o.w = f2tf32(v.w);
        reinterpret_cast<uint4*>(g_Bcvt)[j] = o;
    }
}

// ---------------------------------------------------------------------------
// Kernel 1: preact = A' @ B'^T via tf32 mma, cp.async 3-stage pipeline.
//
// Natural-order smem tiles (row stride BK=16 floats = 64B). Fragment LDS.128
// at [row][4*tg] yields k = {4tg..4tg+3}. mma k-slot consistency only needs
// A and B lanes to agree on logical k per slot, so:
//   mma step 0 uses (.x -> slot tg, .y -> slot tg+4): k set {0,1,4,5,8,9,12,13}
//   mma step 1 uses (.z, .w):                         k set {2,3,6,7,10,11,14,15}
// Together they cover the 16-k tile. Conflict-free: rows g,g+1 x 4 tg span
// exactly 128B per 8-lane LDS phase.
// ---------------------------------------------------------------------------
__global__ __launch_bounds__(256, 1)
void lstm_gemm_tf32_kernel()
{
    __shared__ float As[STAGES][BM * BK];   // 3 x 8KB
    __shared__ float Bs[STAGES][BN * BK];   // 3 x 8KB  -> 48KB total (exact)

    const int tid = threadIdx.x;
    const int bm  = blockIdx.y * BM;
    const int bn  = blockIdx.x * BN;

    const int wid    = tid >> 5;
    const int warp_m = wid >> 2;        // 0..1  (64 rows each)
    const int warp_n = wid & 3;         // 0..3  (32 cols each)
    const int lane   = tid & 31;
    const int g      = lane >> 2;       // 0..7
    const int tg     = lane & 3;        // 0..3

    // staging coords: 2 x 16B of A and 2 x 16B of B per thread per k-tile
    const int r0 = tid >> 2;            // rows 0..63 (and +64)
    const int c0 = tid & 3;             // 16B chunk 0..3

    const unsigned int sA = (unsigned int)__cvta_generic_to_shared(&As[0][0]);
    const unsigned int sB = (unsigned int)__cvta_generic_to_shared(&Bs[0][0]);

    float acc[4][4][4];
#pragma unroll
    for (int mt = 0; mt < 4; mt++)
#pragma unroll
        for (int nt = 0; nt < 4; nt++)
#pragma unroll
            for (int i = 0; i < 4; i++) acc[mt][nt][i] = 0.f;

    // issue one k-tile's cp.asyncs into stage s
    auto issue = [&](int t, int s) {
#pragma unroll
        for (int i = 0; i < 2; i++) {
            const int r = r0 + i * 64;
            const float* ga = &g_Acvt[(size_t)(bm + r) * KTOT + t * BK + 4 * c0];
            const float* gb = &g_Bcvt[(size_t)(bn + r) * KTOT + t * BK + 4 * c0];
            const unsigned int da = sA + (unsigned int)((s * BM * BK + r * BK + 4 * c0) * 4);
            const unsigned int db = sB + (unsigned int)((s * BN * BK + r * BK + 4 * c0) * 4);
            asm volatile("cp.async.cg.shared.global [%0], [%1], 16;\n" :: "r"(da), "l"(ga));
            asm volatile("cp.async.cg.shared.global [%0], [%1], 16;\n" :: "r"(db), "l"(gb));
        }
        asm volatile("cp.async.commit_group;\n" ::: "memory");
    };

    // prologue: tiles 0 and 1 in flight
    issue(0, 0);
    issue(1, 1);

#pragma unroll 1
    for (int t = 0; t < NIT; ++t) {
        // groups committed so far: tiles 0..t+1 -> wait_group 1 ensures tile t done
        asm volatile("cp.async.wait_group 1;\n" ::: "memory");
        __syncthreads();

        if (t + 2 < NIT) {
            issue(t + 2, (t + 2) % STAGES);
        } else {
            asm volatile("cp.async.commit_group;\n" ::: "memory");   // empty group
        }

        const int s = t % STAGES;
        uint4 afr[4][2];
        uint4 bfr[4];
#pragma unroll
        for (int mt = 0; mt < 4; mt++) {
            const int rr = warp_m * 64 + mt * 16 + g;
            afr[mt][0] = *reinterpret_cast<const uint4*>(&As[s][rr * BK + 4 * tg]);
            afr[mt][1] = *reinterpret_cast<const uint4*>(&As[s][(rr + 8) * BK + 4 * tg]);
        }
#pragma unroll
        for (int nt = 0; nt < 4; nt++) {
            const int cc = warp_n * 32 + nt * 8 + g;
            bfr[nt] = *reinterpret_cast<const uint4*>(&Bs[s][cc * BK + 4 * tg]);
        }
#pragma unroll
        for (int mt = 0; mt < 4; mt++) {
#pragma unroll
            for (int nt = 0; nt < 4; nt++) {
                mma_tf32(acc[mt][nt][0], acc[mt][nt][1], acc[mt][nt][2], acc[mt][nt][3],
                         afr[mt][0].x, afr[mt][1].x, afr[mt][0].y, afr[mt][1].y,
                         bfr[nt].x, bfr[nt].y);
                mma_tf32(acc[mt][nt][0], acc[mt][nt][1], acc[mt][nt][2], acc[mt][nt][3],
                         afr[mt][0].z, afr[mt][1].z, afr[mt][0].w, afr[mt][1].w,
                         bfr[nt].z, bfr[nt].w);
            }
        }
    }

    // epilogue: c0,c1 at row g; c2,c3 at row g+8 (mapping unchanged)
#pragma unroll
    for (int mt = 0; mt < 4; mt++) {
#pragma unroll
        for (int nt = 0; nt < 4; nt++) {
            const int gr = bm + warp_m * 64 + mt * 16 + g;
            const int gc = bn + warp_n * 32 + nt * 8 + 2 * tg;
            float2 v0 = make_float2(acc[mt][nt][0], acc[mt][nt][1]);
            float2 v1 = make_float2(acc[mt][nt][2], acc[mt][nt][3]);
            *reinterpret_cast<float2*>(&g_preact[(size_t)gr * NDIM + gc]) = v0;
            *reinterpret_cast<float2*>(&g_preact[(size_t)(gr + 8) * NDIM + gc]) = v1;
        }
    }
}

// ---------------------------------------------------------------------------
// Kernel 2: gates + cell update + LayerNorm + outputs. One block per row.
// (measured 17.7us, DRAM-bound as modeled — unchanged)
// ---------------------------------------------------------------------------
__device__ __forceinline__ float sigmoidf_(float v) {
    return 1.f / (1.f + __expf(-v));
}

__global__ __launch_bounds__(256)
void lstm_cell_ln_kernel(const float* __restrict__ c_in,
                         const float* __restrict__ b_ih,
                         const float* __restrict__ b_hh,
                         const float* __restrict__ ln_w,
                         const float* __restrict__ ln_b,
                         float* __restrict__ h_out,
                         float* __restrict__ c_out)
{
    const int row = blockIdx.x;
    const int tid = threadIdx.x;
    const float* P = g_preact + (size_t)row * NDIM;

    float ct[4], og[4];
    float s = 0.f, s2 = 0.f;

#pragma unroll
    for (int t = 0; t < 4; t++) {
        const int col = tid + t * 256;
        const float pi = P[col]           + __ldg(&b_ih[col])           + __ldg(&b_hh[col]);
        const float pf = P[col + HID]     + __ldg(&b_ih[col + HID])     + __ldg(&b_hh[col + HID]);
        const float po = P[col + 2 * HID] + __ldg(&b_ih[col + 2 * HID]) + __ldg(&b_hh[col + 2 * HID]);
        const float pg = P[col + 3 * HID] + __ldg(&b_ih[col + 3 * HID]) + __ldg(&b_hh[col + 3 * HID]);

        const float ig = sigmoidf_(pi);
        const float fg = sigmoidf_(pf);
        og[t]          = sigmoidf_(po);
        const float gg = tanhf(pg);

        const float cv = c_in[(size_t)row * HID + col] * fg + ig * gg;
        ct[t] = cv;
        s  += cv;
        s2 += cv * cv;
    }

#pragma unroll
    for (int o = 16; o > 0; o >>= 1) {
        s  += __shfl_xor_sync(0xffffffffu, s,  o);
        s2 += __shfl_xor_sync(0xffffffffu, s2, o);
    }
    __shared__ float ws[8], ws2[8];
    const int lane = tid & 31, wid = tid >> 5;
    if (lane == 0) { ws[wid] = s; ws2[wid] = s2; }
    __syncthreads();
    s = 0.f; s2 = 0.f;
#pragma unroll
    for (int w = 0; w < 8; w++) { s += ws[w]; s2 += ws2[w]; }

    const float mu   = s * (1.f / HID);
    const float var  = fmaxf(s2 * (1.f / HID) - mu * mu, 0.f);
    const float rstd = rsqrtf(var + 1e-5f);

#pragma unroll
    for (int t = 0; t < 4; t++) {
        const int col = tid + t * 256;
        const float cn = (ct[t] - mu) * rstd * __ldg(&ln_w[col]) + __ldg(&ln_b[col]);
        c_out[(size_t)row * HID + col] = cn;
        h_out[(size_t)row * HID + col] = og[t] * tanhf(cn);
    }
}

// ---------------------------------------------------------------------------
extern "C" void kernel_launch(void* const* d_in, const int* in_sizes, int n_in,
                              void* d_out, int out_size)
{
    const float* x   = (const float*)d_in[0];
    const float* h   = (const float*)d_in[1];
    const float* c   = (const float*)d_in[2];
    const float* Wih = (const float*)d_in[3];
    const float* bih = (const float*)d_in[4];
    const float* Whh = (const float*)d_in[5];
    const float* bhh = (const float*)d_in[6];
    const float* lnw = (const float*)d_in[7];
    const float* lnb = (const float*)d_in[8];

    float* out   = (float*)d_out;
    float* h_out = out;                          // h_t first
    float* c_out = out + (size_t)BATCH * HID;    // then c_t

    // 3M float4 conversions: exactly 12288 blocks x 256 threads
    cvt_pack_kernel<<<12288, 256>>>(x, h, Wih, Whh);

    dim3 ggrid(NDIM / BN, BATCH / BM);           // 32 x 16 = 512 blocks
    lstm_gemm_tf32_kernel<<<ggrid, 256>>>();
    lstm_cell_ln_kernel<<<BATCH, 256>>>(c, bih, bhh, lnw, lnb, h_out, c_out);
}